// round 13
// baseline (speedup 1.0000x reference)
#include <cuda_runtime.h>
#include <math.h>

#define Bdim 4
#define Ndim 48
#define Rdim 16
#define Tdim 33
#define NCdim 80
#define NIdim 5
#define NN (Ndim * Ndim)          // 2304
#define NEGV -1000.0f
#define HROWS 24                  // rows per dp CTA (half split)
#define PITCH 49                  // conflict-free row-major pitch
#define NTHR 144
#define NBLK 640                  // 80 * 4 * 2
#define PREP_CTAS 512
#define PREP_ROWS 18              // 512*18 = 9216 = B*NN; 2304 % 18 == 0

// g_M[b,t][u*48+v] = trans[b,u,v,t]
__device__ float g_M[Bdim * Tdim * NN];
// scratch: exp(path score) per [b, c, xy]
__device__ float g_scratch[Bdim * NCdim * NN];

// ---- sense-reversing grid barrier (co-residency guaranteed: 5 warps+23KB -> 9 CTAs/SM max, need 4.3) ----
__device__ unsigned g_bar_count = 0;
__device__ unsigned g_bar_gen   = 0;

__device__ __forceinline__ void grid_barrier()
{
    __syncthreads();
    if (threadIdx.x == 0) {
        __threadfence();
        const unsigned gen = *(volatile unsigned*)&g_bar_gen;
        if (atomicAdd(&g_bar_count, 1u) == NBLK - 1u) {
            g_bar_count = 0;
            __threadfence();
            *(volatile unsigned*)&g_bar_gen = gen + 1u;
        } else {
            while (*(volatile unsigned*)&g_bar_gen == gen) {}
        }
        __threadfence();
    }
    __syncthreads();
}

__global__ __launch_bounds__(NTHR, 5)
void fused_kernel(const float* __restrict__ trans,
                  const int*   __restrict__ rules,
                  const int*   __restrict__ type_mask,
                  const float* __restrict__ weights,
                  const float* __restrict__ biases,
                  float*       __restrict__ out)
{
    __shared__ float A0[HROWS * PITCH];        // prep tile / hop0 slice / S slice
    __shared__ float B1[NN];                   // hop1 (full)
    __shared__ float B2[NN];                   // hop2 (full)

    const int tid = threadIdx.x;
    const int pid = blockIdx.x;

    // ============ phase 1: transpose [B*2304, 33] -> g_M ============
    if (pid < PREP_CTAS) {
        const int b    = pid >> 7;             // /128
        const int row0 = (pid & 127) * PREP_ROWS;

        const float* src = trans + ((size_t)b * NN + row0) * Tdim;
        #pragma unroll
        for (int i = tid; i < PREP_ROWS * Tdim; i += NTHR)
            A0[i] = __ldg(src + i);            // fully coalesced
        __syncthreads();

        float* dst = g_M + (size_t)b * Tdim * NN + row0;
        #pragma unroll
        for (int i = tid; i < PREP_ROWS * Tdim; i += NTHR) {
            const int t = i / PREP_ROWS;
            const int r = i - t * PREP_ROWS;
            dst[(size_t)t * NN + r] = A0[r * Tdim + t];   // stride-33 smem: conflict-free
        }
    }
    grid_barrier();

    // ============ phase 2: max-plus DP (R10 mapping) ============
    {
        const int c    = pid % NCdim;
        const int rest = pid / NCdim;          // 0..7
        const int b    = rest >> 1;
        const int rowbase = (rest & 1) * HROWS;

        const int oct = tid / HROWS;           // 0..5
        const int xr  = tid - oct * HROWS;     // 0..23

        const int r0 = __ldg(rules + c * 3 + 0);
        const int r1 = __ldg(rules + c * 3 + 1);
        const int r2 = __ldg(rules + c * 3 + 2);

        const float*  h0 = g_M + (size_t)(b * Tdim + r0) * NN + rowbase * Ndim;
        const float4* h1 = (const float4*)(g_M + (size_t)(b * Tdim + r1) * NN);
        const float4* h2 = (const float4*)(g_M + (size_t)(b * Tdim + r2) * NN);

        float4* B14 = (float4*)B1;
        float4* B24 = (float4*)B2;
        #pragma unroll
        for (int j = 0; j < 4; j++) {
            B14[tid + j * NTHR] = h1[tid + j * NTHR];
            B24[tid + j * NTHR] = h2[tid + j * NTHR];
        }
        #pragma unroll
        for (int i = tid; i < HROWS * Ndim; i += NTHR) {
            const int u = i / Ndim;
            const int v = i - u * Ndim;
            A0[u * PITCH + v] = h0[i];         // coalesced gmem read
        }
        __syncthreads();

        float a0, a1, a2, a3, a4, a5, a6, a7;
        a0 = a1 = a2 = a3 = a4 = a5 = a6 = a7 = -INFINITY;

        const float* ap  = A0 + xr * PITCH;
        const float* bp1 = B1 + oct * 8;

        // stage 1: S[x][oct*8..+7] = max_k hop0[x][k] + hop1[k][..]
        #pragma unroll 8
        for (int k = 0; k < Ndim; k++) {
            const float  av  = ap[k];                              // conflict-free
            const float4 bv0 = *(const float4*)(bp1 + k * Ndim);   // warp-broadcast
            const float4 bv1 = *(const float4*)(bp1 + k * Ndim + 4);
            a0 = fmaxf(a0, av + bv0.x); a1 = fmaxf(a1, av + bv0.y);
            a2 = fmaxf(a2, av + bv0.z); a3 = fmaxf(a3, av + bv0.w);
            a4 = fmaxf(a4, av + bv1.x); a5 = fmaxf(a5, av + bv1.y);
            a6 = fmaxf(a6, av + bv1.z); a7 = fmaxf(a7, av + bv1.w);
        }
        __syncthreads();                       // all A0 reads done

        {
            float* sp = A0 + xr * PITCH + oct * 8;
            sp[0] = a0; sp[1] = a1; sp[2] = a2; sp[3] = a3;
            sp[4] = a4; sp[5] = a5; sp[6] = a6; sp[7] = a7;
        }
        __syncthreads();

        // stage 2: out[x][oct*8..+7] = exp(max_k S[x][k] + hop2[k][..])
        a0 = a1 = a2 = a3 = a4 = a5 = a6 = a7 = -INFINITY;
        const float* bp2 = B2 + oct * 8;

        #pragma unroll 8
        for (int k = 0; k < Ndim; k++) {
            const float  av  = ap[k];                              // S row, conflict-free
            const float4 bv0 = *(const float4*)(bp2 + k * Ndim);   // warp-broadcast
            const float4 bv1 = *(const float4*)(bp2 + k * Ndim + 4);
            a0 = fmaxf(a0, av + bv0.x); a1 = fmaxf(a1, av + bv0.y);
            a2 = fmaxf(a2, av + bv0.z); a3 = fmaxf(a3, av + bv0.w);
            a4 = fmaxf(a4, av + bv1.x); a5 = fmaxf(a5, av + bv1.y);
            a6 = fmaxf(a6, av + bv1.z); a7 = fmaxf(a7, av + bv1.w);
        }

        float* op = g_scratch + ((size_t)b * NCdim + c) * NN + (rowbase + xr) * Ndim + oct * 8;
        *(float4*)(op + 0) = make_float4(__expf(a0), __expf(a1), __expf(a2), __expf(a3));
        *(float4*)(op + 4) = make_float4(__expf(a4), __expf(a5), __expf(a6), __expf(a7));
    }
    grid_barrier();

    // ============ phase 3: combine + mask (R10 g-grouped, fully coalesced) ============
    if (pid < 256) {
        const int task = pid * NTHR + tid;     // 0..36863
        const int g    = task & 3;
        const int bxy  = task >> 2;
        const int xy   = bxy % NN;
        const int b    = bxy / NN;

        const float* wp = weights + g * 20;
        const float* bp = biases  + g * 4;

        float acc0 = __ldg(bp + 0);
        float acc1 = __ldg(bp + 1);
        float acc2 = __ldg(bp + 2);
        float acc3 = __ldg(bp + 3);

        const float* sp = g_scratch + ((size_t)b * NCdim + g * 20) * NN + xy;
        #pragma unroll
        for (int j = 0; j < 5; j++) {
            acc0 = fmaf(sp[(j +  0) * NN], __ldg(wp + j +  0), acc0);
            acc1 = fmaf(sp[(j +  5) * NN], __ldg(wp + j +  5), acc1);
            acc2 = fmaf(sp[(j + 10) * NN], __ldg(wp + j + 10), acc2);
            acc3 = fmaf(sp[(j + 15) * NN], __ldg(wp + j + 15), acc3);
        }

        const int4 m = *(const int4*)(type_mask + (size_t)bxy * Rdim + g * 4);
        float4 o;
        o.x = (m.x == 0) ? acc0 : NEGV;
        o.y = (m.y == 0) ? acc1 : NEGV;
        o.z = (m.z == 0) ? acc2 : NEGV;
        o.w = (m.w == 0) ? acc3 : NEGV;
        *(float4*)(out + (size_t)bxy * Rdim + g * 4) = o;
    }
}

extern "C" void kernel_launch(void* const* d_in, const int* in_sizes, int n_in,
                              void* d_out, int out_size)
{
    const float* transitions = (const float*)d_in[0];
    const int*   type_mask   = (const int*)  d_in[1];
    const int*   rules       = (const int*)  d_in[2];
    const float* weights     = (const float*)d_in[3];
    const float* biases      = (const float*)d_in[4];
    float* out = (float*)d_out;

    fused_kernel<<<NBLK, NTHR>>>(transitions, rules, type_mask,
                                 weights, biases, out);
}